// round 1
// baseline (speedup 1.0000x reference)
#include <cuda_runtime.h>

// Problem constants from setup_inputs(): x is (16, 2, 1024, 1024) fp32, 20 steps.
#define HH 1024
#define WW 1024
#define NPLANES 32              // 16 batch * 2 channels
#define PLANE_ELEMS (HH * WW)
#define TIME_STEPS 20

// 128 MB ping-pong scratch (device global — allocation-free).
__device__ float g_scratch[NPLANES * PLANE_ELEMS];

// One block per (row, plane). 256 threads, each produces 4 consecutive outputs
// via float4 loads of the center/up/down rows. Reflect padding:
//   row -1 -> row 1, row H -> row H-2, col -1 -> col 1, col W -> col W-2.
__global__ __launch_bounds__(256, 8)
void stencil_step(const float* __restrict__ src,
                  float* __restrict__ dst,
                  const float* __restrict__ wgt)
{
    const int row = blockIdx.x;
    const int img = blockIdx.y;
    const int t   = threadIdx.x;          // 0..255 -> columns 4t..4t+3
    const int ch  = img & 1;              // channel index (weights per channel)

    // Weight layout: (2,1,3,3) OIHW -> wgt[ch*9 + ky*3 + kx].
    // Cross-correlation (lax conv): out(y,x) = sum w[ky][kx] * in[y+ky-1][x+kx-1].
    const float* wp = wgt + ch * 9;
    const float wu = __ldg(wp + 1);   // (ky=0, kx=1) -> up
    const float wl = __ldg(wp + 3);   // (ky=1, kx=0) -> left
    const float wc = __ldg(wp + 4);   // center
    const float wr = __ldg(wp + 5);   // right
    const float wd = __ldg(wp + 7);   // (ky=2, kx=1) -> down

    const float* plane = src + (size_t)img * PLANE_ELEMS;
    const int up = (row == 0)      ? 1      : row - 1;
    const int dn = (row == HH - 1) ? HH - 2 : row + 1;

    const float4* rowC = (const float4*)(plane + (size_t)row * WW);
    const float4* rowU = (const float4*)(plane + (size_t)up  * WW);
    const float4* rowD = (const float4*)(plane + (size_t)dn  * WW);

    const float4 cc = rowC[t];
    const float4 uu = rowU[t];
    const float4 dd = rowD[t];

    // Horizontal halo: scalar loads for the two flanking elements (L1-resident —
    // they live in the same/adjacent cache lines as the float4 loads above).
    const int x0 = t * 4;
    const float left  = (t == 0)           ? cc.y : __ldg(plane + (size_t)row * WW + x0 - 1);
    const float right = (t == WW / 4 - 1)  ? cc.z : __ldg(plane + (size_t)row * WW + x0 + 4);

    float4 o;
    o.x = fmaf(wl, left, fmaf(wr, cc.y, fmaf(wu, uu.x, fmaf(wd, dd.x, wc * cc.x))));
    o.y = fmaf(wl, cc.x, fmaf(wr, cc.z, fmaf(wu, uu.y, fmaf(wd, dd.y, wc * cc.y))));
    o.z = fmaf(wl, cc.y, fmaf(wr, cc.w, fmaf(wu, uu.z, fmaf(wd, dd.z, wc * cc.z))));
    o.w = fmaf(wl, cc.z, fmaf(wr, right, fmaf(wu, uu.w, fmaf(wd, dd.w, wc * cc.w))));

    ((float4*)(dst + (size_t)img * PLANE_ELEMS + (size_t)row * WW))[t] = o;
}

extern "C" void kernel_launch(void* const* d_in, const int* in_sizes, int n_in,
                              void* d_out, int out_size)
{
    const float* x   = (const float*)d_in[0];
    const float* wgt = (const float*)d_in[1];
    float* out = (float*)d_out;

    float* scratch = nullptr;
    cudaGetSymbolAddress((void**)&scratch, g_scratch);

    dim3 grid(HH, NPLANES);
    dim3 block(WW / 4);

    // Ping-pong: even steps write scratch, odd steps write d_out.
    // TIME_STEPS = 20 (even) -> step 19 (odd) lands in d_out.
    const float* src = x;
    for (int s = 0; s < TIME_STEPS; ++s) {
        float* dst = ((s & 1) == 0) ? scratch : out;
        stencil_step<<<grid, block>>>(src, dst, wgt);
        src = dst;
    }
}

// round 2
// speedup vs baseline: 1.3372x; 1.3372x over previous
#include <cuda_runtime.h>

// x: (16, 2, 1024, 1024) fp32, 20 diffusion steps, depthwise 5-point stencil,
// reflect padding. Temporal blocking: K=5 fused steps per pass, 4 passes.
#define HH 1024
#define WW 1024
#define NPLANES 32
#define PLANE_ELEMS (HH * WW)
#define K 5            // fused timesteps per kernel pass
#define RB 128         // output rows per block
#define NPASS 4        // 4 * 5 = 20 steps

// 128 MB ping-pong scratch (device global — allocation-free).
__device__ float g_scratch[NPLANES * PLANE_ELEMS];

__device__ __forceinline__ int reflect_row(int i) {
    i = (i < 0) ? -i : i;
    return (i >= HH) ? (2 * HH - 2 - i) : i;
}

// One block: full width (1024 cols = 256 threads * float4) x RB output rows.
// Sweeps RB + 2K input rows; K-stage register pipeline (2-row window/stage).
// Horizontal neighbors: warp shuffles; warp boundaries via tiny smem exchange
// (double-buffered, one __syncthreads per row). Reflect handled via mirrored
// input row indices (valid because the stencil is symmetric: iterating a
// symmetric stencil commutes with mirror extension of the field).
__global__ __launch_bounds__(256, 2)
void fused_stencil(const float* __restrict__ src,
                   float* __restrict__ dst,
                   const float* __restrict__ wgt)
{
    // edge exchange: b[s].x of lane0 / b[s].w of lane31, per warp, double-buffered
    __shared__ float eX[2][K][8];
    __shared__ float eW[2][K][8];

    const int band = blockIdx.x;
    const int img  = blockIdx.y;
    const int t    = threadIdx.x;     // column group: cols 4t..4t+3
    const int lane = t & 31;
    const int warp = t >> 5;

    const int ch = img & 1;           // depthwise: weights per channel
    const float* wp = wgt + ch * 9;   // OIHW (2,1,3,3)
    const float wu = wp[1];
    const float wl = wp[3];
    const float wc = wp[4];
    const float wr = wp[5];
    const float wd = wp[7];

    const float* sp = src + (size_t)img * PLANE_ELEMS;
    float*       dp = dst + (size_t)img * PLANE_ELEMS;

    const int r0 = band * RB;

    // Rolling window per stage s (0..K-1): a[s] = u_s[row-2], b[s] = u_s[row-1]
    float4 a[K], b[K];
#pragma unroll
    for (int s = 0; s < K; ++s) {
        a[s] = make_float4(0.f, 0.f, 0.f, 0.f);
        b[s] = make_float4(0.f, 0.f, 0.f, 0.f);
    }

    const int niter = RB + 2 * K;   // 138

#pragma unroll 2
    for (int m = 0; m < niter; ++m) {
        const int i = r0 - K + m;   // input row index for stage 0

        float4 cur[K + 1];
        cur[0] = ((const float4*)(sp + (size_t)reflect_row(i) * WW))[t];

        const int rd = m & 1;       // edge buffer written at end of iter m-1

#pragma unroll
        for (int s = 1; s <= K; ++s) {
            const float4 bb = b[s - 1];   // u_{s-1}[j]   (center row)
            const float4 aa = a[s - 1];   // u_{s-1}[j-1] (up)
            const float4 dd = cur[s - 1]; // u_{s-1}[j+1] (down)

            float lv = __shfl_up_sync(0xffffffffu, bb.w, 1);
            float rv = __shfl_down_sync(0xffffffffu, bb.x, 1);
            if (lane == 0)  lv = (t == 0)   ? bb.y : eW[rd][s - 1][warp - 1];
            if (lane == 31) rv = (t == 255) ? bb.z : eX[rd][s - 1][warp + 1];

            float4 o;
            o.x = fmaf(wu, aa.x, fmaf(wd, dd.x, fmaf(wl, lv,   fmaf(wr, bb.y, wc * bb.x))));
            o.y = fmaf(wu, aa.y, fmaf(wd, dd.y, fmaf(wl, bb.x, fmaf(wr, bb.z, wc * bb.y))));
            o.z = fmaf(wu, aa.z, fmaf(wd, dd.z, fmaf(wl, bb.y, fmaf(wr, bb.w, wc * bb.z))));
            o.w = fmaf(wu, aa.w, fmaf(wd, dd.w, fmaf(wl, bb.z, fmaf(wr, rv,   wc * bb.w))));
            cur[s] = o;
        }

        // Final-stage row j = i - K lands in the band exactly when m >= 2K.
        if (m >= 2 * K) {
            ((float4*)(dp + (size_t)(i - K) * WW))[t] = cur[K];
        }

        // Shift windows; publish new edge values for next iteration.
#pragma unroll
        for (int s = 0; s < K; ++s) {
            a[s] = b[s];
            b[s] = cur[s];
        }
        const int wrb = (m + 1) & 1;
        if (lane == 0) {
#pragma unroll
            for (int s = 0; s < K; ++s) eX[wrb][s][warp] = b[s].x;
        }
        if (lane == 31) {
#pragma unroll
            for (int s = 0; s < K; ++s) eW[wrb][s][warp] = b[s].w;
        }
        __syncthreads();
    }
}

extern "C" void kernel_launch(void* const* d_in, const int* in_sizes, int n_in,
                              void* d_out, int out_size)
{
    const float* x   = (const float*)d_in[0];
    const float* wgt = (const float*)d_in[1];
    float* out = (float*)d_out;

    float* scratch = nullptr;
    cudaGetSymbolAddress((void**)&scratch, g_scratch);

    dim3 grid(HH / RB, NPLANES);   // 8 bands x 32 planes = 256 blocks
    dim3 block(WW / 4);            // 256 threads

    // 4 passes of 5 fused steps: x -> scratch -> out -> scratch -> out
    fused_stencil<<<grid, block>>>(x,       scratch, wgt);
    fused_stencil<<<grid, block>>>(scratch, out,     wgt);
    fused_stencil<<<grid, block>>>(out,     scratch, wgt);
    fused_stencil<<<grid, block>>>(scratch, out,     wgt);
}

// round 3
// speedup vs baseline: 1.7772x; 1.3290x over previous
#include <cuda_runtime.h>

// x: (16, 2, 1024, 1024) fp32, 20 diffusion steps, depthwise 5-point stencil,
// reflect padding. Temporal blocking: K=5 fused steps per pass, 4 passes.
// Round 3: prefetch-depth-2 row loads to take DRAM latency off the per-row
// critical path (the per-row __syncthreads prevents cross-iteration hiding).
#define HH 1024
#define WW 1024
#define NPLANES 32
#define PLANE_ELEMS (HH * WW)
#define K 5            // fused timesteps per kernel pass
#define RB 128         // output rows per block

// 128 MB ping-pong scratch (device global — allocation-free).
__device__ float g_scratch[NPLANES * PLANE_ELEMS];

__device__ __forceinline__ int reflect_row(int i) {
    i = (i < 0) ? -i : i;
    return (i >= HH) ? (2 * HH - 2 - i) : i;
}

__global__ __launch_bounds__(256, 2)
void fused_stencil(const float* __restrict__ src,
                   float* __restrict__ dst,
                   const float* __restrict__ wgt)
{
    // Per-warp edge exchange (lane0 .x / lane31 .w), double-buffered per row.
    __shared__ float eX[2][K][8];
    __shared__ float eW[2][K][8];

    const int band = blockIdx.x;
    const int img  = blockIdx.y;
    const int t    = threadIdx.x;     // column group: cols 4t..4t+3
    const int lane = t & 31;
    const int warp = t >> 5;

    const float* wp = wgt + (img & 1) * 9;   // OIHW (2,1,3,3), depthwise
    const float wu = wp[1];
    const float wl = wp[3];
    const float wc = wp[4];
    const float wr = wp[5];
    const float wd = wp[7];

    const float* sp = src + (size_t)img * PLANE_ELEMS;
    float*       dp = dst + (size_t)img * PLANE_ELEMS;

    const int r0 = band * RB;

    // Rolling window per stage s: a[s] = u_s[row-2], b[s] = u_s[row-1]
    float4 a[K], b[K];
#pragma unroll
    for (int s = 0; s < K; ++s) {
        a[s] = make_float4(0.f, 0.f, 0.f, 0.f);
        b[s] = make_float4(0.f, 0.f, 0.f, 0.f);
    }

    // Zero edge buffers so iteration 0 reads match b == 0.
    if (t < 2 * K * 8) {
        ((float*)eX)[t] = 0.f;
        ((float*)eW)[t] = 0.f;
    }
    __syncthreads();

    const int niter = RB + 2 * K;   // 138

    // Prefetch pipeline, depth 2: loads leave the per-iteration critical path.
    float4 p0 = ((const float4*)(sp + (size_t)reflect_row(r0 - K)     * WW))[t];
    float4 p1 = ((const float4*)(sp + (size_t)reflect_row(r0 - K + 1) * WW))[t];

#pragma unroll 2
    for (int m = 0; m < niter; ++m) {
        const int i = r0 - K + m;   // input row index for stage 0

        float4 cur[K + 1];
        cur[0] = p0;
        p0 = p1;
        if (m + 2 < niter) {
            p1 = ((const float4*)(sp + (size_t)reflect_row(i + 2) * WW))[t];
        }

        const int rd = m & 1;       // edge buffer written at end of iter m-1

#pragma unroll
        for (int s = 1; s <= K; ++s) {
            const float4 bb = b[s - 1];   // u_{s-1}[j]   (center)
            const float4 aa = a[s - 1];   // u_{s-1}[j-1] (up)
            const float4 dd = cur[s - 1]; // u_{s-1}[j+1] (down)

            float lv = __shfl_up_sync(0xffffffffu, bb.w, 1);
            float rv = __shfl_down_sync(0xffffffffu, bb.x, 1);
            if (lane == 0)  lv = (t == 0)   ? bb.y : eW[rd][s - 1][warp - 1];
            if (lane == 31) rv = (t == 255) ? bb.z : eX[rd][s - 1][warp + 1];

            float4 o;
            o.x = fmaf(wu, aa.x, fmaf(wd, dd.x, fmaf(wl, lv,   fmaf(wr, bb.y, wc * bb.x))));
            o.y = fmaf(wu, aa.y, fmaf(wd, dd.y, fmaf(wl, bb.x, fmaf(wr, bb.z, wc * bb.y))));
            o.z = fmaf(wu, aa.z, fmaf(wd, dd.z, fmaf(wl, bb.y, fmaf(wr, bb.w, wc * bb.z))));
            o.w = fmaf(wu, aa.w, fmaf(wd, dd.w, fmaf(wl, bb.z, fmaf(wr, rv,   wc * bb.w))));
            cur[s] = o;
        }

        // Final-stage row j = i - K is a band row exactly when m >= 2K.
        if (m >= 2 * K) {
            ((float4*)(dp + (size_t)(i - K) * WW))[t] = cur[K];
        }

        // Shift windows; publish edges for next iteration (other parity).
#pragma unroll
        for (int s = 0; s < K; ++s) {
            a[s] = b[s];
            b[s] = cur[s];
        }
        const int wrb = (m + 1) & 1;
        if (lane == 0) {
#pragma unroll
            for (int s = 0; s < K; ++s) eX[wrb][s][warp] = b[s].x;
        }
        if (lane == 31) {
#pragma unroll
            for (int s = 0; s < K; ++s) eW[wrb][s][warp] = b[s].w;
        }
        __syncthreads();
    }
}

extern "C" void kernel_launch(void* const* d_in, const int* in_sizes, int n_in,
                              void* d_out, int out_size)
{
    const float* x   = (const float*)d_in[0];
    const float* wgt = (const float*)d_in[1];
    float* out = (float*)d_out;

    float* scratch = nullptr;
    cudaGetSymbolAddress((void**)&scratch, g_scratch);

    dim3 grid(HH / RB, NPLANES);   // 8 bands x 32 planes = 256 blocks
    dim3 block(WW / 4);            // 256 threads

    // 4 passes of 5 fused steps: x -> scratch -> out -> scratch -> out
    fused_stencil<<<grid, block>>>(x,       scratch, wgt);
    fused_stencil<<<grid, block>>>(scratch, out,     wgt);
    fused_stencil<<<grid, block>>>(out,     scratch, wgt);
    fused_stencil<<<grid, block>>>(scratch, out,     wgt);
}